// round 3
// baseline (speedup 1.0000x reference)
#include <cuda_runtime.h>

#define AA 64
#define NN 128
#define HH 8
#define GG 4
#define THREADS 256
#define OUTW (AA - 1)          // 63
#define OUT_PER (AA * OUTW)    // 4032 floats per (t,b) tile
#define OUT4_PER (OUT_PER / 4) // 1008 float4
#define SROW 33                // state row stride in float4 (132 floats, padded)
#define AROW 68                // s_att row stride in floats (padded)

typedef unsigned long long u64;

// ---- packed f32x2 helpers (Blackwell FFMA2) ----
__device__ __forceinline__ u64 pk2(float lo, float hi) {
    u64 r;
    asm("mov.b64 %0, {%1, %2};" : "=l"(r) : "f"(lo), "f"(hi));
    return r;
}
__device__ __forceinline__ void upk2(u64 v, float &lo, float &hi) {
    asm("mov.b64 {%0, %1}, %2;" : "=f"(lo), "=f"(hi) : "l"(v));
}
__device__ __forceinline__ void ffma2(u64 &d, u64 a, u64 b) {
    asm("fma.rn.f32x2 %0, %1, %2, %0;" : "+l"(d) : "l"(a), "l"(b));
}
__device__ __forceinline__ void add2(u64 &d, u64 a) {
    asm("add.rn.f32x2 %0, %1, %0;" : "+l"(d) : "l"(a));
}

__global__ void __launch_bounds__(THREADS, 4)
attn_kernel(const float* __restrict__ state,
            const float* __restrict__ Wq, const float* __restrict__ bq,
            const float* __restrict__ Wk, const float* __restrict__ bk,
            float* __restrict__ out)
{
    // weights packed: s_w[n*16 + 0..7] = Wq[n][0..7], s_w[n*16 + 8..15] = Wk[n][0..7]
    __shared__ __align__(16) float s_w[NN * 16];        // 8 KB
    __shared__ __align__(16) float s_u[AA * SROW * 4];  // 33 KB: state tile, aliased by s_att
    __shared__ __align__(16) float s_q[AA * HH];        // 2 KB
    __shared__ __align__(16) float s_k[AA * HH];        // 2 KB  (dense (A,H): reshape trick)

    float* const s_att = s_u;  // 64*68 floats fits inside s_u

    const int tid = threadIdx.x;
    const int blk = blockIdx.x;

    for (int i = tid; i < NN * HH; i += THREADS) {
        const int n = i >> 3, h = i & 7;
        s_w[n * 16 + h]     = Wq[i];
        s_w[n * 16 + 8 + h] = Wk[i];
    }

    const int row = tid >> 2;   // 0..63
    const int sub = tid & 3;    // 0..3
    // projection mapping: (row, mat, n-half)
    const int mat = sub >> 1;   // 0 = Q, 1 = K
    const int nh  = sub & 1;    // n-half: [0,64) or [64,128)

    // bias seeds (added only by the nh==0 lane of each pair)
    const float* bb = mat ? bk : bq;
    const u64 z = 0ull;
    const u64 seed0 = nh ? z : pk2(__ldg(bb + 0), __ldg(bb + 1));
    const u64 seed1 = nh ? z : pk2(__ldg(bb + 2), __ldg(bb + 3));
    const u64 seed2 = nh ? z : pk2(__ldg(bb + 4), __ldg(bb + 5));
    const u64 seed3 = nh ? z : pk2(__ldg(bb + 6), __ldg(bb + 7));

    // weight base for this thread: ulonglong2 index = n*4 + mat*2 (+0/+1)
    const ulonglong2* const wbase =
        ((const ulonglong2*)s_w) + (nh * (NN / 2)) * 4 + mat * 2;

    const int jbase = sub * 16;

    for (int g = 0; g < GG; g++) {
        // ---------------- Phase 0: coalesced stage of state tile ----------
        const float4* gsrc =
            (const float4*)(state + ((size_t)(blk * GG + g)) * (AA * NN));
        #pragma unroll
        for (int k = 0; k < 8; k++) {
            const int idx = k * THREADS + tid;   // 0..2047
            const int r = idx >> 5, c = idx & 31; // warp == one row: 512B coalesced
            ((float4*)s_u)[r * SROW + c] = gsrc[idx];
        }
        __syncthreads();

        // ---------------- Phase 1: Q/K projection -------------------------
        u64 a0 = seed0, a1 = seed1, a2 = seed2, a3 = seed3;
        const float4* xrow = ((const float4*)s_u) + row * SROW + nh * 16;
        #pragma unroll
        for (int i = 0; i < 16; i++) {
            const float4 x = xrow[i];
            u64 xx;
            {
                const ulonglong2 wA = wbase[(i * 4 + 0) * 4];
                const ulonglong2 wB = wbase[(i * 4 + 0) * 4 + 1];
                xx = pk2(x.x, x.x);
                ffma2(a0, xx, wA.x); ffma2(a1, xx, wA.y);
                ffma2(a2, xx, wB.x); ffma2(a3, xx, wB.y);
            }
            {
                const ulonglong2 wA = wbase[(i * 4 + 1) * 4];
                const ulonglong2 wB = wbase[(i * 4 + 1) * 4 + 1];
                xx = pk2(x.y, x.y);
                ffma2(a0, xx, wA.x); ffma2(a1, xx, wA.y);
                ffma2(a2, xx, wB.x); ffma2(a3, xx, wB.y);
            }
            {
                const ulonglong2 wA = wbase[(i * 4 + 2) * 4];
                const ulonglong2 wB = wbase[(i * 4 + 2) * 4 + 1];
                xx = pk2(x.z, x.z);
                ffma2(a0, xx, wA.x); ffma2(a1, xx, wA.y);
                ffma2(a2, xx, wB.x); ffma2(a3, xx, wB.y);
            }
            {
                const ulonglong2 wA = wbase[(i * 4 + 3) * 4];
                const ulonglong2 wB = wbase[(i * 4 + 3) * 4 + 1];
                xx = pk2(x.w, x.w);
                ffma2(a0, xx, wA.x); ffma2(a1, xx, wA.y);
                ffma2(a2, xx, wB.x); ffma2(a3, xx, wB.y);
            }
        }
        // reduce across the n-halves (partner = lane^1)
        add2(a0, __shfl_xor_sync(0xffffffffu, a0, 1));
        add2(a1, __shfl_xor_sync(0xffffffffu, a1, 1));
        add2(a2, __shfl_xor_sync(0xffffffffu, a2, 1));
        add2(a3, __shfl_xor_sync(0xffffffffu, a3, 1));

        if (nh == 0) {
            float o0, o1, o2, o3, o4, o5, o6, o7;
            upk2(a0, o0, o1); upk2(a1, o2, o3);
            upk2(a2, o4, o5); upk2(a3, o6, o7);
            float* dst = (mat ? s_k : s_q) + row * HH;
            *(float4*)(dst)     = make_float4(o0, o1, o2, o3);
            *(float4*)(dst + 4) = make_float4(o4, o5, o6, o7);
        }
        __syncthreads();
        // s_u (state) is now dead; s_att may overwrite it.

        // ---------------- Phase 2: att = q @ reshape(k), softmax ----------
        {
            const float* qrow = s_q + row * HH;
            const float4 qa = *(const float4*)qrow;
            const float4 qb = *(const float4*)(qrow + 4);
            const float qr[8] = {qa.x, qa.y, qa.z, qa.w, qb.x, qb.y, qb.z, qb.w};

            u64 at2[8];
            #pragma unroll
            for (int p = 0; p < 8; p++) at2[p] = 0ull;

            // reshape trick: kr[h][j] = k_flat[h*64 + j]  (s_k dense, stride HH)
            #pragma unroll
            for (int h = 0; h < HH; h++) {
                const u64 qq = pk2(qr[h], qr[h]);
                const ulonglong2* kp = (const ulonglong2*)(s_k + h * AA + jbase);
                const ulonglong2 k0 = kp[0], k1 = kp[1], k2 = kp[2], k3 = kp[3];
                ffma2(at2[0], qq, k0.x); ffma2(at2[1], qq, k0.y);
                ffma2(at2[2], qq, k1.x); ffma2(at2[3], qq, k1.y);
                ffma2(at2[4], qq, k2.x); ffma2(at2[5], qq, k2.y);
                ffma2(at2[6], qq, k3.x); ffma2(at2[7], qq, k3.y);
            }

            float a[16];
            #pragma unroll
            for (int p = 0; p < 8; p++) upk2(at2[p], a[2 * p], a[2 * p + 1]);

            float m = a[0];
            #pragma unroll
            for (int c = 1; c < 16; c++) m = fmaxf(m, a[c]);
            m = fmaxf(m, __shfl_xor_sync(0xffffffffu, m, 1));
            m = fmaxf(m, __shfl_xor_sync(0xffffffffu, m, 2));

            float s = 0.f;
            #pragma unroll
            for (int c = 0; c < 16; c++) { a[c] = __expf(a[c] - m); s += a[c]; }
            s += __shfl_xor_sync(0xffffffffu, s, 1);
            s += __shfl_xor_sync(0xffffffffu, s, 2);
            const float rinv = __frcp_rn(s);

            float4* arow = (float4*)(s_att + row * AROW + jbase);
            arow[0] = make_float4(a[0]  * rinv, a[1]  * rinv, a[2]  * rinv, a[3]  * rinv);
            arow[1] = make_float4(a[4]  * rinv, a[5]  * rinv, a[6]  * rinv, a[7]  * rinv);
            arow[2] = make_float4(a[8]  * rinv, a[9]  * rinv, a[10] * rinv, a[11] * rinv);
            arow[3] = make_float4(a[12] * rinv, a[13] * rinv, a[14] * rinv, a[15] * rinv);
        }
        __syncthreads();

        // ---------------- Phase 3: off-diagonal gather, coalesced store ---
        float4* o4p = (float4*)(out + (size_t)(blk * GG + g) * OUT_PER);
        #pragma unroll
        for (int it = 0; it < 4; it++) {
            const int o4 = it * THREADS + tid;
            if (o4 < OUT4_PER) {
                const unsigned o = (unsigned)o4 * 4u;
                float v[4];
                #pragma unroll
                for (int c = 0; c < 4; c++) {
                    const unsigned oc = o + c;
                    const unsigned rr = oc / OUTW;
                    const unsigned jj = oc - rr * OUTW;
                    const unsigned j  = jj + (jj >= rr ? 1u : 0u);
                    v[c] = s_att[rr * AROW + j];
                }
                o4p[o4] = make_float4(v[0], v[1], v[2], v[3]);
            }
        }
        __syncthreads();  // before next g overwrites s_u/s_att
    }
}

extern "C" void kernel_launch(void* const* d_in, const int* in_sizes, int n_in,
                              void* d_out, int out_size) {
    const float* state = (const float*)d_in[0];
    const float* Wq    = (const float*)d_in[1];
    const float* bq    = (const float*)d_in[2];
    const float* Wk    = (const float*)d_in[3];
    const float* bk    = (const float*)d_in[4];
    float* out = (float*)d_out;

    const int tb = in_sizes[0] / (AA * NN);  // T*B = 16384
    attn_kernel<<<tb / GG, THREADS>>>(state, Wq, bq, Wk, bk, out);
}

// round 4
// speedup vs baseline: 1.1339x; 1.1339x over previous
#include <cuda_runtime.h>

#define AA 64
#define NN 128
#define HH 8
#define THREADS 256
#define OUTW (AA - 1)          // 63
#define OUT_PER (AA * OUTW)    // 4032 floats per (t,b) tile
#define OUT4_PER (OUT_PER / 4) // 1008 float4
#define AROW 68                // s_att row stride (68 mod 32 = 4 -> conflict-free-ish)

typedef unsigned long long u64;

// ---- packed f32x2 helpers (Blackwell FFMA2/FADD2) ----
__device__ __forceinline__ u64 pk2(float lo, float hi) {
    u64 r;
    asm("mov.b64 %0, {%1, %2};" : "=l"(r) : "f"(lo), "f"(hi));
    return r;
}
__device__ __forceinline__ void upk2(u64 v, float &lo, float &hi) {
    asm("mov.b64 {%0, %1}, %2;" : "=f"(lo), "=f"(hi) : "l"(v));
}
__device__ __forceinline__ void ffma2(u64 &d, u64 a, u64 b) {
    asm("fma.rn.f32x2 %0, %1, %2, %0;" : "+l"(d) : "l"(a), "l"(b));
}
__device__ __forceinline__ u64 fadd2(u64 a, u64 b) {
    u64 r;
    asm("add.rn.f32x2 %0, %1, %2;" : "=l"(r) : "l"(a), "l"(b));
    return r;
}

__global__ void __launch_bounds__(THREADS, 2)
attn_kernel(const float* __restrict__ state,
            const float* __restrict__ Wq, const float* __restrict__ bq,
            const float* __restrict__ Wk, const float* __restrict__ bk,
            float* __restrict__ out)
{
    // s_big: first 2048 floats serve as packed weight staging (s_w),
    // later reused as the 64x68 attention matrix (s_att).
    __shared__ __align__(16) float s_big[AA * AROW];  // 17408 B
    __shared__ __align__(16) float s_q[AA * HH];      // 2 KB
    __shared__ __align__(16) float s_k[AA * HH];      // 2 KB (dense (A,H): reshape trick)

    float* const s_w   = s_big;
    float* const s_att = s_big;

    const int tid  = threadIdx.x;
    const int lane = tid & 31;
    const int warp = tid >> 5;
    const int blk  = blockIdx.x;

    // ---- Stage packed weights: s_w[n*16 + 0..7] = Wq[n][:], +8..15 = Wk[n][:]
    for (int i = tid; i < NN * HH; i += THREADS) {
        const int n = i >> 3, h = i & 7;
        s_w[n * 16 + h]     = Wq[i];
        s_w[n * 16 + 8 + h] = Wk[i];
    }
    __syncthreads();

    // ---- Pull this lane's weight slice into registers: n = 4*lane .. 4*lane+3,
    //      w[j][p] = (W[n][2p], W[n][2p+1]); p 0..3 = Q h-pairs, p 4..7 = K h-pairs.
    u64 w[4][8];
    #pragma unroll
    for (int j = 0; j < 4; j++) {
        const float4* p4 = (const float4*)(s_w + (lane * 4 + j) * 16);
        const float4 a = p4[0], b = p4[1], c = p4[2], d = p4[3];
        w[j][0] = pk2(a.x, a.y); w[j][1] = pk2(a.z, a.w);
        w[j][2] = pk2(b.x, b.y); w[j][3] = pk2(b.z, b.w);
        w[j][4] = pk2(c.x, c.y); w[j][5] = pk2(c.z, c.w);
        w[j][6] = pk2(d.x, d.y); w[j][7] = pk2(d.z, d.w);
    }

    // Per-lane final output slot after reduce-scatter (bit-reversed low 4 bits)
    const int hidx = ((lane & 1) << 3) | ((lane & 2) << 1) |
                     ((lane & 4) >> 1) | ((lane & 8) >> 3);
    float bias = 0.f;
    float* qkdst = s_q;  // dummy
    if (lane < 16) {
        if (hidx < 8) { bias = __ldg(bq + hidx);     qkdst = s_q + hidx;     }
        else          { bias = __ldg(bk + hidx - 8); qkdst = s_k + hidx - 8; }
    }

    const bool b0 = lane & 1, b1 = lane & 2, b2 = lane & 4, b3 = lane & 8;

    // ---------------- Phase 1: Q/K projection (warp-per-row) ----------------
    // Warp w handles rows w*8 .. w*8+7; one coalesced LDG.128 per row.
    const float4* xbase =
        (const float4*)(state + (size_t)blk * (AA * NN)) + (warp * 8) * 32 + lane;

    #pragma unroll 2
    for (int r8 = 0; r8 < 8; r8++) {
        const float4 x = xbase[r8 * 32];

        u64 acc[8];
        #pragma unroll
        for (int p = 0; p < 8; p++) acc[p] = 0ull;

        u64 xx;
        xx = pk2(x.x, x.x);
        #pragma unroll
        for (int p = 0; p < 8; p++) ffma2(acc[p], xx, w[0][p]);
        xx = pk2(x.y, x.y);
        #pragma unroll
        for (int p = 0; p < 8; p++) ffma2(acc[p], xx, w[1][p]);
        xx = pk2(x.z, x.z);
        #pragma unroll
        for (int p = 0; p < 8; p++) ffma2(acc[p], xx, w[2][p]);
        xx = pk2(x.w, x.w);
        #pragma unroll
        for (int p = 0; p < 8; p++) ffma2(acc[p], xx, w[3][p]);

        // ---- reduce-scatter across the warp (16 h values -> 1 per lane<16)
        u64 r1[4];
        #pragma unroll
        for (int j = 0; j < 4; j++) {
            const u64 send = b0 ? acc[j] : acc[j + 4];
            const u64 recv = __shfl_xor_sync(0xffffffffu, send, 1);
            const u64 keep = b0 ? acc[j + 4] : acc[j];
            r1[j] = fadd2(keep, recv);
        }
        u64 r2[2];
        #pragma unroll
        for (int j = 0; j < 2; j++) {
            const u64 send = b1 ? r1[j] : r1[j + 2];
            const u64 recv = __shfl_xor_sync(0xffffffffu, send, 2);
            const u64 keep = b1 ? r1[j + 2] : r1[j];
            r2[j] = fadd2(keep, recv);
        }
        u64 r3;
        {
            const u64 send = b2 ? r2[0] : r2[1];
            const u64 recv = __shfl_xor_sync(0xffffffffu, send, 4);
            const u64 keep = b2 ? r2[1] : r2[0];
            r3 = fadd2(keep, recv);
        }
        float f0, f1;
        upk2(r3, f0, f1);
        {
            const float send = b3 ? f0 : f1;
            const float recv = __shfl_xor_sync(0xffffffffu, send, 8);
            const float keep = b3 ? f1 : f0;
            f0 = keep + recv;
        }
        f0 += __shfl_xor_sync(0xffffffffu, f0, 16);

        if (lane < 16) qkdst[(warp * 8 + r8) * HH] = f0 + bias;
    }
    __syncthreads();

    // -------- Phase 2: att = q @ reshape(k), softmax (thread = row-quarter) --
    {
        const int row = tid >> 2;       // 0..63
        const int sub = tid & 3;        // 0..3 -> 16-col quarter
        const int jbase = sub * 16;

        const float* qrow = s_q + row * HH;
        const float4 qa = *(const float4*)qrow;
        const float4 qb = *(const float4*)(qrow + 4);
        const float qr[8] = {qa.x, qa.y, qa.z, qa.w, qb.x, qb.y, qb.z, qb.w};

        u64 at2[8];
        #pragma unroll
        for (int p = 0; p < 8; p++) at2[p] = 0ull;

        // reshape trick: kr[h][j] = k_flat[h*64 + j] (s_k is the flat (A,H) buffer)
        #pragma unroll
        for (int h = 0; h < HH; h++) {
            const u64 qq = pk2(qr[h], qr[h]);
            const ulonglong2* kp = (const ulonglong2*)(s_k + h * AA + jbase);
            const ulonglong2 k0 = kp[0], k1 = kp[1], k2 = kp[2], k3 = kp[3];
            ffma2(at2[0], qq, k0.x); ffma2(at2[1], qq, k0.y);
            ffma2(at2[2], qq, k1.x); ffma2(at2[3], qq, k1.y);
            ffma2(at2[4], qq, k2.x); ffma2(at2[5], qq, k2.y);
            ffma2(at2[6], qq, k3.x); ffma2(at2[7], qq, k3.y);
        }

        float a[16];
        #pragma unroll
        for (int p = 0; p < 8; p++) upk2(at2[p], a[2 * p], a[2 * p + 1]);

        float m = a[0];
        #pragma unroll
        for (int c = 1; c < 16; c++) m = fmaxf(m, a[c]);
        m = fmaxf(m, __shfl_xor_sync(0xffffffffu, m, 1));
        m = fmaxf(m, __shfl_xor_sync(0xffffffffu, m, 2));

        float s = 0.f;
        #pragma unroll
        for (int c = 0; c < 16; c++) { a[c] = __expf(a[c] - m); s += a[c]; }
        s += __shfl_xor_sync(0xffffffffu, s, 1);
        s += __shfl_xor_sync(0xffffffffu, s, 2);
        const float rinv = __frcp_rn(s);

        float4* arow = (float4*)(s_att + row * AROW + jbase);
        arow[0] = make_float4(a[0]  * rinv, a[1]  * rinv, a[2]  * rinv, a[3]  * rinv);
        arow[1] = make_float4(a[4]  * rinv, a[5]  * rinv, a[6]  * rinv, a[7]  * rinv);
        arow[2] = make_float4(a[8]  * rinv, a[9]  * rinv, a[10] * rinv, a[11] * rinv);
        arow[3] = make_float4(a[12] * rinv, a[13] * rinv, a[14] * rinv, a[15] * rinv);
    }
    __syncthreads();

    // -------- Phase 3: off-diagonal gather, coalesced float4 stores ---------
    float4* o4p = (float4*)(out + (size_t)blk * OUT_PER);
    #pragma unroll
    for (int it = 0; it < 4; it++) {
        const int o4 = it * THREADS + tid;
        if (o4 < OUT4_PER) {
            const unsigned o = (unsigned)o4 * 4u;
            float v[4];
            #pragma unroll
            for (int c = 0; c < 4; c++) {
                const unsigned oc = o + c;
                const unsigned rr = oc / OUTW;
                const unsigned jj = oc - rr * OUTW;
                const unsigned j  = jj + (jj >= rr ? 1u : 0u);
                v[c] = s_att[rr * AROW + j];
            }
            o4p[o4] = make_float4(v[0], v[1], v[2], v[3]);
        }
    }
}

extern "C" void kernel_launch(void* const* d_in, const int* in_sizes, int n_in,
                              void* d_out, int out_size) {
    const float* state = (const float*)d_in[0];
    const float* Wq    = (const float*)d_in[1];
    const float* bq    = (const float*)d_in[2];
    const float* Wk    = (const float*)d_in[3];
    const float* bk    = (const float*)d_in[4];
    float* out = (float*)d_out;

    const int tb = in_sizes[0] / (AA * NN);  // T*B = 16384 tiles
    attn_kernel<<<tb, THREADS>>>(state, Wq, bq, Wk, bk, out);
}

// round 5
// speedup vs baseline: 1.4911x; 1.3151x over previous
#include <cuda_runtime.h>

#define AA 64
#define NN 128
#define HH 8
#define THREADS 256
#define OUTW (AA - 1)          // 63
#define OUT_PER (AA * OUTW)    // 4032 floats per (t,b) tile
#define OUT4_PER (OUT_PER / 4) // 1008 float4
#define SR4 33                 // stage row stride in float4 (pad: banks (r+i)&7)
#define AROW 68                // s_att row stride in floats

typedef unsigned long long u64;

// ---- packed f32x2 helpers (Blackwell FFMA2) ----
__device__ __forceinline__ u64 pk2(float lo, float hi) {
    u64 r;
    asm("mov.b64 %0, {%1, %2};" : "=l"(r) : "f"(lo), "f"(hi));
    return r;
}
__device__ __forceinline__ void upk2(u64 v, float &lo, float &hi) {
    asm("mov.b64 {%0, %1}, %2;" : "=f"(lo), "=f"(hi) : "l"(v));
}
__device__ __forceinline__ void ffma2(u64 &d, u64 a, u64 b) {
    asm("fma.rn.f32x2 %0, %1, %2, %0;" : "+l"(d) : "l"(a), "l"(b));
}

__global__ void __launch_bounds__(THREADS, 4)
attn_kernel(const float* __restrict__ state,
            const float* __restrict__ Wq, const float* __restrict__ bq,
            const float* __restrict__ Wk, const float* __restrict__ bk,
            float* __restrict__ out)
{
    __shared__ __align__(16) float4 s_x4[AA * SR4];  // 33792 B stage; aliased by s_att
    __shared__ __align__(16) float  s_w[NN * 16];    // 8 KB packed weights
    __shared__ __align__(16) float  s_q[AA * HH];    // 2 KB
    __shared__ __align__(16) float  s_k[AA * HH];    // 2 KB (dense (A,H): reshape trick)

    float* const s_att = (float*)s_x4;               // 64*68 floats <= stage size

    const int tid = threadIdx.x;
    const int blk = blockIdx.x;

    // ---- weights: s_w[n*16 + 0..7] = Wq[n][:], s_w[n*16 + 8..15] = Wk[n][:]
    //      sub s reads 16B at n*16 + s*4  (s0:q[0:4], s1:q[4:8], s2:k[0:4], s3:k[4:8])
    for (int i = tid; i < NN * HH; i += THREADS) {
        const int n = i >> 3, h = i & 7;
        s_w[n * 16 + h]     = Wq[i];
        s_w[n * 16 + 8 + h] = Wk[i];
    }

    // ---- Phase 0: coalesced stage (warp == one row: 512B contiguous)
    const float4* gsrc = (const float4*)(state + (size_t)blk * (AA * NN));
    #pragma unroll
    for (int k = 0; k < 8; k++) {
        const int idx = k * THREADS + tid;   // 0..2047
        const int r = idx >> 5, c = idx & 31;
        s_x4[r * SR4 + c] = gsrc[idx];
    }
    __syncthreads();

    // ---- Phase 1: projection. thread = (row, sub) ; sub = h-quad
    const int row = tid >> 2;
    const int sub = tid & 3;
    const int jbase = sub * 16;

    const float* bptr = ((sub < 2) ? bq : bk) + (sub & 1) * 4;
    u64 a0 = pk2(__ldg(bptr + 0), __ldg(bptr + 1));
    u64 a1 = pk2(__ldg(bptr + 2), __ldg(bptr + 3));

    {
        const float4* xr = s_x4 + row * SR4;
        const ulonglong2* wp = ((const ulonglong2*)s_w) + sub;  // [n*4 + sub]
        #pragma unroll 8
        for (int i = 0; i < 32; i++) {
            const float4 x = xr[i];                       // 1 slot (broadcast x4)
            u64 xx;
            ulonglong2 w;
            w = wp[(i * 4 + 0) * 4];                      // 1 slot (64B/warp)
            xx = pk2(x.x, x.x); ffma2(a0, xx, w.x); ffma2(a1, xx, w.y);
            w = wp[(i * 4 + 1) * 4];
            xx = pk2(x.y, x.y); ffma2(a0, xx, w.x); ffma2(a1, xx, w.y);
            w = wp[(i * 4 + 2) * 4];
            xx = pk2(x.z, x.z); ffma2(a0, xx, w.x); ffma2(a1, xx, w.y);
            w = wp[(i * 4 + 3) * 4];
            xx = pk2(x.w, x.w); ffma2(a0, xx, w.x); ffma2(a1, xx, w.y);
        }
    }
    {
        float o0, o1, o2, o3;
        upk2(a0, o0, o1); upk2(a1, o2, o3);
        float* dst = ((sub < 2) ? s_q : s_k) + row * HH + (sub & 1) * 4;
        *(float4*)dst = make_float4(o0, o1, o2, o3);
    }
    __syncthreads();
    // stage buffer is dead now; s_att may overwrite it.

    // ---- Phase 2: att = q @ reshape(k), softmax
    {
        const float* qrow = s_q + row * HH;
        const float4 qa = *(const float4*)qrow;
        const float4 qb = *(const float4*)(qrow + 4);
        const float qr[8] = {qa.x, qa.y, qa.z, qa.w, qb.x, qb.y, qb.z, qb.w};

        u64 at2[8];
        #pragma unroll
        for (int p = 0; p < 8; p++) at2[p] = 0ull;

        // reshape trick: kr[h][j] = k_flat[h*64 + j] (s_k is the flat (A,H) buffer)
        #pragma unroll
        for (int h = 0; h < HH; h++) {
            const u64 qq = pk2(qr[h], qr[h]);
            const ulonglong2* kp = (const ulonglong2*)(s_k + h * AA + jbase);
            const ulonglong2 k0 = kp[0], k1 = kp[1], k2 = kp[2], k3 = kp[3];
            ffma2(at2[0], qq, k0.x); ffma2(at2[1], qq, k0.y);
            ffma2(at2[2], qq, k1.x); ffma2(at2[3], qq, k1.y);
            ffma2(at2[4], qq, k2.x); ffma2(at2[5], qq, k2.y);
            ffma2(at2[6], qq, k3.x); ffma2(at2[7], qq, k3.y);
        }

        float a[16];
        #pragma unroll
        for (int p = 0; p < 8; p++) upk2(at2[p], a[2 * p], a[2 * p + 1]);

        float m = a[0];
        #pragma unroll
        for (int c = 1; c < 16; c++) m = fmaxf(m, a[c]);
        m = fmaxf(m, __shfl_xor_sync(0xffffffffu, m, 1));
        m = fmaxf(m, __shfl_xor_sync(0xffffffffu, m, 2));

        float s = 0.f;
        #pragma unroll
        for (int c = 0; c < 16; c++) { a[c] = __expf(a[c] - m); s += a[c]; }
        s += __shfl_xor_sync(0xffffffffu, s, 1);
        s += __shfl_xor_sync(0xffffffffu, s, 2);
        const float rinv = __frcp_rn(s);

        float4* arow = (float4*)(s_att + row * AROW + jbase);
        arow[0] = make_float4(a[0]  * rinv, a[1]  * rinv, a[2]  * rinv, a[3]  * rinv);
        arow[1] = make_float4(a[4]  * rinv, a[5]  * rinv, a[6]  * rinv, a[7]  * rinv);
        arow[2] = make_float4(a[8]  * rinv, a[9]  * rinv, a[10] * rinv, a[11] * rinv);
        arow[3] = make_float4(a[12] * rinv, a[13] * rinv, a[14] * rinv, a[15] * rinv);
    }
    __syncthreads();

    // ---- Phase 3: off-diagonal gather, coalesced float4 stores
    float4* o4p = (float4*)(out + (size_t)blk * OUT_PER);
    #pragma unroll
    for (int it = 0; it < 4; it++) {
        const int o4 = it * THREADS + tid;
        if (o4 < OUT4_PER) {
            const unsigned o = (unsigned)o4 * 4u;
            float v[4];
            #pragma unroll
            for (int c = 0; c < 4; c++) {
                const unsigned oc = o + c;
                const unsigned rr = oc / OUTW;
                const unsigned jj = oc - rr * OUTW;
                const unsigned j  = jj + (jj >= rr ? 1u : 0u);
                v[c] = s_att[rr * AROW + j];
            }
            o4p[o4] = make_float4(v[0], v[1], v[2], v[3]);
        }
    }
}

extern "C" void kernel_launch(void* const* d_in, const int* in_sizes, int n_in,
                              void* d_out, int out_size) {
    const float* state = (const float*)d_in[0];
    const float* Wq    = (const float*)d_in[1];
    const float* bq    = (const float*)d_in[2];
    const float* Wk    = (const float*)d_in[3];
    const float* bk    = (const float*)d_in[4];
    float* out = (float*)d_out;

    const int tb = in_sizes[0] / (AA * NN);  // T*B = 16384 tiles
    attn_kernel<<<tb, THREADS>>>(state, Wq, bq, Wk, bk, out);
}

// round 6
// speedup vs baseline: 2.1291x; 1.4278x over previous
#include <cuda_runtime.h>

#define AA 64
#define NN 128
#define HH 8
#define THREADS 256
#define OUTW (AA - 1)          // 63
#define OUT_PER (AA * OUTW)    // 4032 floats per (t,b) tile
#define OUT4_PER (OUT_PER / 4) // 1008 float4
#define SR4 33                 // stage row stride in float4
#define AROW 68                // s_att row stride in floats
#define SQR 12                 // s_q row stride in floats (16B aligned, conflict-free)

typedef unsigned long long u64;

// ---- packed f32x2 helpers (Blackwell FFMA2) ----
__device__ __forceinline__ u64 pk2(float lo, float hi) {
    u64 r;
    asm("mov.b64 %0, {%1, %2};" : "=l"(r) : "f"(lo), "f"(hi));
    return r;
}
__device__ __forceinline__ void upk2(u64 v, float &lo, float &hi) {
    asm("mov.b64 {%0, %1}, %2;" : "=f"(lo), "=f"(hi) : "l"(v));
}
__device__ __forceinline__ void ffma2(u64 &d, u64 a, u64 b) {
    asm("fma.rn.f32x2 %0, %1, %2, %0;" : "+l"(d) : "l"(a), "l"(b));
}

__global__ void __launch_bounds__(THREADS, 4)
attn_kernel(const float* __restrict__ state,
            const float* __restrict__ Wq, const float* __restrict__ bq,
            const float* __restrict__ Wk, const float* __restrict__ bk,
            float* __restrict__ out)
{
    __shared__ __align__(16) float4 s_x4[AA * SR4];  // 33792 B stage; aliased by s_att
    __shared__ __align__(16) float  s_w[NN * 16];    // 8 KB packed weights
    __shared__ __align__(16) float  s_q[AA * SQR];   // 3 KB (padded rows)
    __shared__ __align__(16) float  s_k[AA * HH];    // 2 KB dense (A,H): reshape trick

    float* const s_att = (float*)s_x4;               // 64*68 floats <= stage size

    const int tid = threadIdx.x;
    const int blk = blockIdx.x;

    // ---- weights: s_w[n*16 + 0..7] = Wq[n][:], s_w[n*16 + 8..15] = Wk[n][:]
    for (int i = tid; i < NN * HH; i += THREADS) {
        const int n = i >> 3, h = i & 7;
        s_w[n * 16 + h]     = Wq[i];
        s_w[n * 16 + 8 + h] = Wk[i];
    }

    // ---- Phase 0: coalesced stage (warp == one row: 512B contiguous)
    const float4* gsrc = (const float4*)(state + (size_t)blk * (AA * NN));
    #pragma unroll
    for (int k = 0; k < 8; k++) {
        const int idx = k * THREADS + tid;   // 0..2047
        const int r = idx >> 5, c = idx & 31;
        s_x4[r * SR4 + c] = gsrc[idx];
    }
    __syncthreads();

    // ---- Phase 1: projection. thread = (sub, row): sub is WARP-UNIFORM ----
    const int p_sub = tid >> 6;   // 0..3, constant within each pair of warps
    const int p_row = tid & 63;   // lanes = 32 consecutive rows

    {
        const float* bptr = ((p_sub < 2) ? bq : bk) + (p_sub & 1) * 4;
        u64 a0 = pk2(__ldg(bptr + 0), __ldg(bptr + 1));
        u64 a1 = pk2(__ldg(bptr + 2), __ldg(bptr + 3));

        const float4* xr = s_x4 + p_row * SR4;                  // dense: 4 cyc
        const ulonglong2* wp = ((const ulonglong2*)s_w) + p_sub; // uniform: bcast
        #pragma unroll 8
        for (int i = 0; i < 32; i++) {
            const float4 x = xr[i];
            u64 xx;
            ulonglong2 w;
            w = wp[(i * 4 + 0) * 4];
            xx = pk2(x.x, x.x); ffma2(a0, xx, w.x); ffma2(a1, xx, w.y);
            w = wp[(i * 4 + 1) * 4];
            xx = pk2(x.y, x.y); ffma2(a0, xx, w.x); ffma2(a1, xx, w.y);
            w = wp[(i * 4 + 2) * 4];
            xx = pk2(x.z, x.z); ffma2(a0, xx, w.x); ffma2(a1, xx, w.y);
            w = wp[(i * 4 + 3) * 4];
            xx = pk2(x.w, x.w); ffma2(a0, xx, w.x); ffma2(a1, xx, w.y);
        }

        float o0, o1, o2, o3;
        upk2(a0, o0, o1); upk2(a1, o2, o3);
        if (p_sub < 2) {
            *(float4*)(s_q + p_row * SQR + (p_sub & 1) * 4) =
                make_float4(o0, o1, o2, o3);
        } else {
            *(float4*)(s_k + p_row * HH + (p_sub & 1) * 4) =
                make_float4(o0, o1, o2, o3);
        }
    }
    __syncthreads();
    // stage buffer is dead; s_att may overwrite it.

    // ---- Phase 2a: raw att quarter in (sub,row): k-loads are warp-uniform --
    {
        const float4 qa = *(const float4*)(s_q + p_row * SQR);
        const float4 qb = *(const float4*)(s_q + p_row * SQR + 4);
        const float qr[8] = {qa.x, qa.y, qa.z, qa.w, qb.x, qb.y, qb.z, qb.w};

        u64 at2[8];
        #pragma unroll
        for (int p = 0; p < 8; p++) at2[p] = 0ull;

        // reshape trick: kr[h][j] = k_flat[h*64 + j]; address uniform per warp
        const int jbase = p_sub * 16;
        #pragma unroll
        for (int h = 0; h < HH; h++) {
            const u64 qq = pk2(qr[h], qr[h]);
            const ulonglong2* kp = (const ulonglong2*)(s_k + h * AA + jbase);
            const ulonglong2 k0 = kp[0], k1 = kp[1], k2 = kp[2], k3 = kp[3];
            ffma2(at2[0], qq, k0.x); ffma2(at2[1], qq, k0.y);
            ffma2(at2[2], qq, k1.x); ffma2(at2[3], qq, k1.y);
            ffma2(at2[4], qq, k2.x); ffma2(at2[5], qq, k2.y);
            ffma2(at2[6], qq, k3.x); ffma2(at2[7], qq, k3.y);
        }

        float a[16];
        #pragma unroll
        for (int p = 0; p < 8; p++) upk2(at2[p], a[2 * p], a[2 * p + 1]);

        float4* arow = (float4*)(s_att + p_row * AROW + jbase);
        arow[0] = make_float4(a[0],  a[1],  a[2],  a[3]);
        arow[1] = make_float4(a[4],  a[5],  a[6],  a[7]);
        arow[2] = make_float4(a[8],  a[9],  a[10], a[11]);
        arow[3] = make_float4(a[12], a[13], a[14], a[15]);
    }
    __syncthreads();

    // ---- Phase 2b: softmax in (row,sub): shfl partners are adjacent lanes --
    {
        const int row = tid >> 2;
        const int sub = tid & 3;
        float4* arow = (float4*)(s_att + row * AROW + sub * 16);
        const float4 v0 = arow[0], v1 = arow[1], v2 = arow[2], v3 = arow[3];
        float a[16] = {v0.x, v0.y, v0.z, v0.w, v1.x, v1.y, v1.z, v1.w,
                       v2.x, v2.y, v2.z, v2.w, v3.x, v3.y, v3.z, v3.w};

        float m = a[0];
        #pragma unroll
        for (int c = 1; c < 16; c++) m = fmaxf(m, a[c]);
        m = fmaxf(m, __shfl_xor_sync(0xffffffffu, m, 1));
        m = fmaxf(m, __shfl_xor_sync(0xffffffffu, m, 2));

        float s = 0.f;
        #pragma unroll
        for (int c = 0; c < 16; c++) { a[c] = __expf(a[c] - m); s += a[c]; }
        s += __shfl_xor_sync(0xffffffffu, s, 1);
        s += __shfl_xor_sync(0xffffffffu, s, 2);
        const float rinv = __frcp_rn(s);

        arow[0] = make_float4(a[0]  * rinv, a[1]  * rinv, a[2]  * rinv, a[3]  * rinv);
        arow[1] = make_float4(a[4]  * rinv, a[5]  * rinv, a[6]  * rinv, a[7]  * rinv);
        arow[2] = make_float4(a[8]  * rinv, a[9]  * rinv, a[10] * rinv, a[11] * rinv);
        arow[3] = make_float4(a[12] * rinv, a[13] * rinv, a[14] * rinv, a[15] * rinv);
    }
    __syncthreads();

    // ---- Phase 3: off-diagonal gather, coalesced float4 stores
    float4* o4p = (float4*)(out + (size_t)blk * OUT_PER);
    #pragma unroll
    for (int it = 0; it < 4; it++) {
        const int o4 = it * THREADS + tid;
        if (o4 < OUT4_PER) {
            const unsigned o = (unsigned)o4 * 4u;
            float v[4];
            #pragma unroll
            for (int c = 0; c < 4; c++) {
                const unsigned oc = o + c;
                const unsigned rr = oc / OUTW;
                const unsigned jj = oc - rr * OUTW;
                const unsigned j  = jj + (jj >= rr ? 1u : 0u);
                v[c] = s_att[rr * AROW + j];
            }
            o4p[o4] = make_float4(v[0], v[1], v[2], v[3]);
        }
    }
}

extern "C" void kernel_launch(void* const* d_in, const int* in_sizes, int n_in,
                              void* d_out, int out_size) {
    const float* state = (const float*)d_in[0];
    const float* Wq    = (const float*)d_in[1];
    const float* bq    = (const float*)d_in[2];
    const float* Wk    = (const float*)d_in[3];
    const float* bk    = (const float*)d_in[4];
    float* out = (float*)d_out;

    const int tb = in_sizes[0] / (AA * NN);  // T*B = 16384 tiles
    attn_kernel<<<tb, THREADS>>>(state, Wq, bq, Wk, bk, out);
}

// round 10
// speedup vs baseline: 2.5660x; 1.2052x over previous
#include <cuda_runtime.h>

#define AA 64
#define NN 128
#define HH 8
#define G2 2
#define THREADS 256
#define OUTW (AA - 1)          // 63
#define OUT_PER (AA * OUTW)    // 4032 floats per (t,b) tile
#define OUT4_PER (OUT_PER / 4) // 1008 float4
#define SR4 33                 // stage row stride in float4
#define AROW 68                // s_att row stride in floats
#define SQR 12                 // s_q row stride in floats

#define ST_F4   (AA * SR4)                 // float4 per staged tile (2112)
#define STAGE_ITERS (G2 * AA * NN / 4 / THREADS)   // 4096 float4 / 256 = 16
#define SMEM_BYTES (G2 * ST_F4 * 16 + NN * 16 * 4 + G2 * AA * SQR * 4 + G2 * AA * HH * 4)

typedef unsigned long long u64;

// ---- packed f32x2 helpers (Blackwell FFMA2) ----
__device__ __forceinline__ u64 pk2(float lo, float hi) {
    u64 r;
    asm("mov.b64 %0, {%1, %2};" : "=l"(r) : "f"(lo), "f"(hi));
    return r;
}
__device__ __forceinline__ void upk2(u64 v, float &lo, float &hi) {
    asm("mov.b64 {%0, %1}, %2;" : "=f"(lo), "=f"(hi) : "l"(v));
}
__device__ __forceinline__ void ffma2(u64 &d, u64 a, u64 b) {
    asm("fma.rn.f32x2 %0, %1, %2, %0;" : "+l"(d) : "l"(a), "l"(b));
}

__global__ void __launch_bounds__(THREADS, 2)
attn_kernel(const float* __restrict__ state,
            const float* __restrict__ Wq, const float* __restrict__ bq,
            const float* __restrict__ Wk, const float* __restrict__ bk,
            float* __restrict__ out)
{
    extern __shared__ __align__(16) unsigned char smem_raw[];
    float4* const s_x4 = (float4*)smem_raw;                       // [G2][ST_F4]
    float*  const s_w  = (float*)(smem_raw + G2 * ST_F4 * 16);    // NN*16
    float*  const s_q  = s_w + NN * 16;                           // [G2][AA*SQR]
    float*  const s_k  = s_q + G2 * AA * SQR;                     // [G2][AA*HH]

    const int tid = threadIdx.x;
    const int blk = blockIdx.x;

    // ---- weights: s_w[n*16 + 0..7] = Wq[n][:], s_w[n*16 + 8..15] = Wk[n][:]
    for (int i = tid; i < NN * HH; i += THREADS) {
        const int n = i >> 3, h = i & 7;
        s_w[n * 16 + h]     = Wq[i];
        s_w[n * 16 + 8 + h] = Wk[i];
    }

    // ---- Phase 0: coalesced stage of BOTH tiles (warp == one row, 512B)
    const float4* gsrc = (const float4*)(state + (size_t)blk * (G2 * AA * NN));
    #pragma unroll
    for (int k = 0; k < STAGE_ITERS; k++) {         // 16 iters, idx 0..4095
        const int idx = k * THREADS + tid;
        const int g = idx >> 11;                    // 0..1
        const int w = (idx >> 5) & 63;              // row within tile
        const int c = idx & 31;
        s_x4[g * ST_F4 + w * SR4 + c] = gsrc[idx];
    }
    __syncthreads();

    // ---- Phase 1: projection. thread = (mat, row); 128 active threads.
    //      mat warp-uniform -> w-LDS broadcast; w reused across both tiles.
    if (tid < 2 * AA) {
        const int mat = tid >> 6;   // 0 = Q, 1 = K (uniform per warp)
        const int row = tid & 63;

        const float* bb = mat ? bk : bq;
        u64 a0[4], a1[4];
        #pragma unroll
        for (int p = 0; p < 4; p++) {
            const u64 seed = pk2(__ldg(bb + 2 * p), __ldg(bb + 2 * p + 1));
            a0[p] = seed; a1[p] = seed;
        }

        const float4* xr0 = s_x4 + row * SR4;
        const float4* xr1 = s_x4 + ST_F4 + row * SR4;
        const ulonglong2* wp = (const ulonglong2*)(s_w + mat * 8); // n stride = 4

        #pragma unroll 4
        for (int i = 0; i < 32; i++) {
            const float4 x0 = xr0[i];
            const float4 x1 = xr1[i];
            u64 xx;
            {
                const ulonglong2 w0 = wp[(4 * i + 0) * 4];
                const ulonglong2 w1 = wp[(4 * i + 0) * 4 + 1];
                xx = pk2(x0.x, x0.x);
                ffma2(a0[0], xx, w0.x); ffma2(a0[1], xx, w0.y);
                ffma2(a0[2], xx, w1.x); ffma2(a0[3], xx, w1.y);
                xx = pk2(x1.x, x1.x);
                ffma2(a1[0], xx, w0.x); ffma2(a1[1], xx, w0.y);
                ffma2(a1[2], xx, w1.x); ffma2(a1[3], xx, w1.y);
            }
            {
                const ulonglong2 w0 = wp[(4 * i + 1) * 4];
                const ulonglong2 w1 = wp[(4 * i + 1) * 4 + 1];
                xx = pk2(x0.y, x0.y);
                ffma2(a0[0], xx, w0.x); ffma2(a0[1], xx, w0.y);
                ffma2(a0[2], xx, w1.x); ffma2(a0[3], xx, w1.y);
                xx = pk2(x1.y, x1.y);
                ffma2(a1[0], xx, w0.x); ffma2(a1[1], xx, w0.y);
                ffma2(a1[2], xx, w1.x); ffma2(a1[3], xx, w1.y);
            }
            {
                const ulonglong2 w0 = wp[(4 * i + 2) * 4];
                const ulonglong2 w1 = wp[(4 * i + 2) * 4 + 1];
                xx = pk2(x0.z, x0.z);
                ffma2(a0[0], xx, w0.x); ffma2(a0[1], xx, w0.y);
                ffma2(a0[2], xx, w1.x); ffma2(a0[3], xx, w1.y);
                xx = pk2(x1.z, x1.z);
                ffma2(a1[0], xx, w0.x); ffma2(a1[1], xx, w0.y);
                ffma2(a1[2], xx, w1.x); ffma2(a1[3], xx, w1.y);
            }
            {
                const ulonglong2 w0 = wp[(4 * i + 3) * 4];
                const ulonglong2 w1 = wp[(4 * i + 3) * 4 + 1];
                xx = pk2(x0.w, x0.w);
                ffma2(a0[0], xx, w0.x); ffma2(a0[1], xx, w0.y);
                ffma2(a0[2], xx, w1.x); ffma2(a0[3], xx, w1.y);
                xx = pk2(x1.w, x1.w);
                ffma2(a1[0], xx, w0.x); ffma2(a1[1], xx, w0.y);
                ffma2(a1[2], xx, w1.x); ffma2(a1[3], xx, w1.y);
            }
        }

        float v0, v1, v2, v3, v4, v5, v6, v7;
        if (mat == 0) {
            upk2(a0[0], v0, v1); upk2(a0[1], v2, v3);
            upk2(a0[2], v4, v5); upk2(a0[3], v6, v7);
            *(float4*)(s_q + row * SQR)     = make_float4(v0, v1, v2, v3);
            *(float4*)(s_q + row * SQR + 4) = make_float4(v4, v5, v6, v7);
            upk2(a1[0], v0, v1); upk2(a1[1], v2, v3);
            upk2(a1[2], v4, v5); upk2(a1[3], v6, v7);
            *(float4*)(s_q + AA * SQR + row * SQR)     = make_float4(v0, v1, v2, v3);
            *(float4*)(s_q + AA * SQR + row * SQR + 4) = make_float4(v4, v5, v6, v7);
        } else {
            upk2(a0[0], v0, v1); upk2(a0[1], v2, v3);
            upk2(a0[2], v4, v5); upk2(a0[3], v6, v7);
            *(float4*)(s_k + row * HH)     = make_float4(v0, v1, v2, v3);
            *(float4*)(s_k + row * HH + 4) = make_float4(v4, v5, v6, v7);
            upk2(a1[0], v0, v1); upk2(a1[1], v2, v3);
            upk2(a1[2], v4, v5); upk2(a1[3], v6, v7);
            *(float4*)(s_k + AA * HH + row * HH)     = make_float4(v0, v1, v2, v3);
            *(float4*)(s_k + AA * HH + row * HH + 4) = make_float4(v4, v5, v6, v7);
        }
    }
    __syncthreads();
    // stage buffers are dead; s_att[g] aliases stage half g.

    // ---- Phase 2a: raw att in (sub,row); k-loads warp-uniform --------------
    {
        const int p_sub = tid >> 6;
        const int p_row = tid & 63;
        const int jbase = p_sub * 16;
        #pragma unroll
        for (int g = 0; g < G2; g++) {
            const float* qg = s_q + g * AA * SQR;
            const float* kg = s_k + g * AA * HH;
            float* attg = (float*)s_x4 + g * (ST_F4 * 4);

            const float4 qa = *(const float4*)(qg + p_row * SQR);
            const float4 qb = *(const float4*)(qg + p_row * SQR + 4);
            const float qr[8] = {qa.x, qa.y, qa.z, qa.w, qb.x, qb.y, qb.z, qb.w};

            u64 at2[8];
            #pragma unroll
            for (int p = 0; p < 8; p++) at2[p] = 0ull;

            // reshape trick: kr[h][j] = k_flat[h*64 + j]; warp-uniform address
            #pragma unroll
            for (int h = 0; h < HH; h++) {
                const u64 qq = pk2(qr[h], qr[h]);
                const ulonglong2* kp = (const ulonglong2*)(kg + h * AA + jbase);
                const ulonglong2 k0 = kp[0], k1 = kp[1], k2 = kp[2], k3 = kp[3];
                ffma2(at2[0], qq, k0.x); ffma2(at2[1], qq, k0.y);
                ffma2(at2[2], qq, k1.x); ffma2(at2[3], qq, k1.y);
                ffma2(at2[4], qq, k2.x); ffma2(at2[5], qq, k2.y);
                ffma2(at2[6], qq, k3.x); ffma2(at2[7], qq, k3.y);
            }

            float a[16];
            #pragma unroll
            for (int p = 0; p < 8; p++) upk2(at2[p], a[2 * p], a[2 * p + 1]);

            float4* arow = (float4*)(attg + p_row * AROW + jbase);
            arow[0] = make_float4(a[0],  a[1],  a[2],  a[3]);
            arow[1] = make_float4(a[4],  a[5],  a[6],  a[7]);
            arow[2] = make_float4(a[8],  a[9],  a[10], a[11]);
            arow[3] = make_float4(a[12], a[13], a[14], a[15]);
        }
    }
    __syncthreads();

    // ---- Phase 2b: softmax in (row,sub); shfl partners adjacent ------------
    {
        const int row = tid >> 2;
        const int sub = tid & 3;
        #pragma unroll
        for (int g = 0; g < G2; g++) {
            float* attg = (float*)s_x4 + g * (ST_F4 * 4);
            float4* arow = (float4*)(attg + row * AROW + sub * 16);
            const float4 v0 = arow[0], v1 = arow[1], v2 = arow[2], v3 = arow[3];
            float a[16] = {v0.x, v0.y, v0.z, v0.w, v1.x, v1.y, v1.z, v1.w,
                           v2.x, v2.y, v2.z, v2.w, v3.x, v3.y, v3.z, v3.w};

            float m = a[0];
            #pragma unroll
            for (int c = 1; c < 16; c++) m = fmaxf(m, a[c]);
            m = fmaxf(m, __shfl_xor_sync(0xffffffffu, m, 1));
            m = fmaxf(m, __shfl_xor_sync(0xffffffffu, m, 2));

            float s = 0.f;
            #pragma unroll
            for (int c = 0; c < 16; c++) { a[c] = __expf(a[c] - m); s += a[c]; }
            s += __shfl_xor_sync(0xffffffffu, s, 1);
            s += __shfl_xor_sync(0xffffffffu, s, 2);
            const float rinv = __frcp_rn(s);

            arow[0] = make_float4(a[0]  * rinv, a[1]  * rinv, a[2]  * rinv, a[3]  * rinv);
            arow[1] = make_float4(a[4]  * rinv, a[5]  * rinv, a[6]  * rinv, a[7]  * rinv);
            arow[2] = make_float4(a[8]  * rinv, a[9]  * rinv, a[10] * rinv, a[11] * rinv);
            arow[3] = make_float4(a[12] * rinv, a[13] * rinv, a[14] * rinv, a[15] * rinv);
        }
    }
    __syncthreads();

    // ---- Phase 3: off-diagonal gather, coalesced float4 stores -------------
    #pragma unroll
    for (int g = 0; g < G2; g++) {
        const float* attg = (const float*)s_x4 + g * (ST_F4 * 4);
        float4* o4p = (float4*)(out + (size_t)(blk * G2 + g) * OUT_PER);
        #pragma unroll
        for (int it = 0; it < 4; it++) {
            const int o4 = it * THREADS + tid;
            if (o4 < OUT4_PER) {
                const unsigned o = (unsigned)o4 * 4u;
                float v[4];
                #pragma unroll
                for (int c = 0; c < 4; c++) {
                    const unsigned oc = o + c;
                    const unsigned rr = oc / OUTW;
                    const unsigned jj = oc - rr * OUTW;
                    const unsigned j  = jj + (jj >= rr ? 1u : 0u);
                    v[c] = attg[rr * AROW + j];
                }
                o4p[o4] = make_float4(v[0], v[1], v[2], v[3]);
            }
        }
    }
}

extern "C" void kernel_launch(void* const* d_in, const int* in_sizes, int n_in,
                              void* d_out, int out_size) {
    const float* state = (const float*)d_in[0];
    const float* Wq    = (const float*)d_in[1];
    const float* bq    = (const float*)d_in[2];
    const float* Wk    = (const float*)d_in[3];
    const float* bk    = (const float*)d_in[4];
    float* out = (float*)d_out;

    // Not a stream op: safe under graph capture; idempotent every call.
    cudaFuncSetAttribute(attn_kernel,
                         cudaFuncAttributeMaxDynamicSharedMemorySize,
                         SMEM_BYTES);

    const int tb = in_sizes[0] / (AA * NN);  // T*B = 16384 tiles
    attn_kernel<<<tb / G2, THREADS, SMEM_BYTES>>>(state, Wq, bq, Wk, bk, out);
}